// round 4
// baseline (speedup 1.0000x reference)
#include <cuda_runtime.h>
#include <cuda_bf16.h>
#include <cstdint>
#include <cstddef>

#define S_LEN 2048
#define R_LEN 384
typedef unsigned long long ull;

__device__ __forceinline__ ull pack2(float lo, float hi) {
    ull r; asm("mov.b64 %0, {%1, %2};" : "=l"(r) : "f"(lo), "f"(hi)); return r;
}
__device__ __forceinline__ float2 unpack2(ull v) {
    float2 f; asm("mov.b64 {%0, %1}, %2;" : "=f"(f.x), "=f"(f.y) : "l"(v)); return f;
}
__device__ __forceinline__ ull dup2(float v) {
    ull r; asm("mov.b64 %0, {%1, %1};" : "=l"(r) : "f"(v)); return r;
}
__device__ __forceinline__ ull ffma2(ull a, ull b, ull c) {
    ull d; asm("fma.rn.f32x2 %0, %1, %2, %3;" : "=l"(d) : "l"(a), "l"(b), "l"(c)); return d;
}
__device__ __forceinline__ float sigmoidf(float x) { return 1.f / (1.f + __expf(-x)); }

struct SmemAB {
    float mst[8][64];    // per-warp LN'd row staging
    float pw[8][512];    // per-warp online-softmax pooled m (also pass-A pool partials)
    float wmax[8][8];
    float wZ[8][8];
    float msum[8];
    float pwt[512];
    float gmax[8];
    float Zt[8];
};
struct SmemC {
    float mp[8][512];    // per-warp: [4 s-pairs][64 d] as f32x2 {m[2p][d], m[2p+1][d]}
    float gost[8][512];  // per-warp: [4 s-pairs][64 hc] gated-o, f32x2 packed
};
struct Smem {
    float Wg[4096];      // [d][hc]
    float Wo[4096];      // [hc][d]
    float Wv[512];       // [d][c]
    float qk[512];       // [h][d]
    union { SmemAB ab; SmemC c; } u;
    float qpool[64];
    float oflat[64];     // o flattened over hc = h*8+c
    float bgs[64];
    float bos[64];
    float qtmp[64];
    float msumtot;
};

__global__ void __launch_bounds__(256, 3)
msa_col_global_attn(const float* __restrict__ Mraw, const float* __restrict__ Mmask,
                    const float* __restrict__ ln_g, const float* __restrict__ ln_b,
                    const float* __restrict__ Wq,   const float* __restrict__ Wk,
                    const float* __restrict__ Wv,   const float* __restrict__ Wg,
                    const float* __restrict__ bg,   const float* __restrict__ Wo,
                    const float* __restrict__ bo,   float* __restrict__ Out)
{
    extern __shared__ char smraw[];
    Smem* sm = (Smem*)smraw;
    const int r    = blockIdx.x;
    const int tid  = threadIdx.x;
    const int lane = tid & 31;
    const int w    = tid >> 5;

    // ---- cooperative weight loads ----
    {
        const float4* g4 = (const float4*)Wg;
        const float4* o4 = (const float4*)Wo;
        float4* sg = (float4*)sm->Wg;
        float4* so = (float4*)sm->Wo;
        #pragma unroll
        for (int i = tid; i < 1024; i += 256) { sg[i] = g4[i]; so[i] = o4[i]; }
        if (tid < 128) ((float4*)sm->Wv)[tid] = ((const float4*)Wv)[tid];
        if (tid < 64)  { sm->bgs[tid] = bg[tid]; sm->bos[tid] = bo[tid]; }
    }
    const float g0 = ln_g[2*lane], g1 = ln_g[2*lane+1];
    const float b0 = ln_b[2*lane], b1 = ln_b[2*lane+1];

    // ================= Pass A: LN + masked mean-pool =================
    {
        float qa0 = 0.f, qa1 = 0.f, msum = 0.f;
        float2 x  = *(const float2*)(Mraw + ((size_t)(w * R_LEN + r)) * 64 + 2*lane);
        float  mk = __ldg(Mmask + (size_t)w * R_LEN + r);
        for (int s = w; s < S_LEN; s += 8) {
            float2 cur = x; float cmk = mk;
            int sn = s + 8;
            if (sn < S_LEN) {
                x  = *(const float2*)(Mraw + ((size_t)(sn * R_LEN + r)) * 64 + 2*lane);
                mk = __ldg(Mmask + (size_t)sn * R_LEN + r);
            }
            float t = cur.x + cur.y, sq = fmaf(cur.x, cur.x, cur.y * cur.y);
            #pragma unroll
            for (int o = 16; o; o >>= 1) {
                t  += __shfl_xor_sync(0xffffffffu, t, o);
                sq += __shfl_xor_sync(0xffffffffu, sq, o);
            }
            float mu   = t * (1.f/64.f);
            float rstd = rsqrtf(fmaf(sq, 1.f/64.f, -mu*mu) + 1e-5f);
            float m0 = fmaf((cur.x - mu) * rstd, g0, b0);
            float m1 = fmaf((cur.y - mu) * rstd, g1, b1);
            qa0 = fmaf(cmk, m0, qa0);
            qa1 = fmaf(cmk, m1, qa1);
            msum += cmk;
        }
        *(float2*)&sm->u.ab.pw[w][2*lane] = make_float2(qa0, qa1);
        if (lane == 0) sm->u.ab.msum[w] = msum;
    }
    __syncthreads();
    if (tid < 64) {
        float a = 0.f;
        #pragma unroll
        for (int ww = 0; ww < 8; ww++) a += sm->u.ab.pw[ww][tid];
        sm->qpool[tid] = a;
    }
    if (tid == 64) {
        float a = 0.f;
        #pragma unroll
        for (int ww = 0; ww < 8; ww++) a += sm->u.ab.msum[ww];
        sm->msumtot = a;
    }
    __syncthreads();

    // q = (pool/msum) @ Wq * C^-0.5  (warp 0)
    if (w == 0) {
        const float inv = 1.f / (sm->msumtot + 1e-10f);
        float q0 = 0.f, q1 = 0.f;
        #pragma unroll 8
        for (int d = 0; d < 64; d++) {
            float qa = sm->qpool[d] * inv;
            float2 wq = __ldg((const float2*)(Wq + d*64 + 2*lane));
            q0 = fmaf(qa, wq.x, q0);
            q1 = fmaf(qa, wq.y, q1);
        }
        const float sc = 0.35355339059327373f;  // 8^-0.5
        sm->qtmp[2*lane]   = q0 * sc;
        sm->qtmp[2*lane+1] = q1 * sc;
    }
    __syncthreads();
    // qk[h][d] = sum_c q[h*8+c] * Wk[d][c]   (warp w handles head h = w)
    {
        const int h = w;
        float a0 = 0.f, a1 = 0.f;
        #pragma unroll
        for (int c = 0; c < 8; c++) {
            float qq = sm->qtmp[h*8 + c];
            a0 = fmaf(qq, __ldg(Wk + lane*8 + c),        a0);
            a1 = fmaf(qq, __ldg(Wk + (lane+32)*8 + c),   a1);
        }
        sm->qk[h*64 + lane]      = a0;
        sm->qk[h*64 + lane + 32] = a1;
    }
    __syncthreads();

    // ================= Pass B: online softmax; pw[h][d] = sum_s w[h,s] m[s,d] =================
    {
        const int myh = lane >> 2, seg = lane & 3;
        const float4 qv0 = *(const float4*)&sm->qk[myh*64 + seg*16 +  0];
        const float4 qv1 = *(const float4*)&sm->qk[myh*64 + seg*16 +  4];
        const float4 qv2 = *(const float4*)&sm->qk[myh*64 + seg*16 +  8];
        const float4 qv3 = *(const float4*)&sm->qk[myh*64 + seg*16 + 12];
        float rmax = -3.4e38f, rZ = 0.f;
        float pwr[16];
        #pragma unroll
        for (int i = 0; i < 16; i++) pwr[i] = 0.f;

        float2 x  = *(const float2*)(Mraw + ((size_t)(w * R_LEN + r)) * 64 + 2*lane);
        float  mk = __ldg(Mmask + (size_t)w * R_LEN + r);
        for (int s = w; s < S_LEN; s += 8) {
            float2 cur = x; float cmk = mk;
            int sn = s + 8;
            if (sn < S_LEN) {
                x  = *(const float2*)(Mraw + ((size_t)(sn * R_LEN + r)) * 64 + 2*lane);
                mk = __ldg(Mmask + (size_t)sn * R_LEN + r);
            }
            float t = cur.x + cur.y, sq = fmaf(cur.x, cur.x, cur.y * cur.y);
            #pragma unroll
            for (int o = 16; o; o >>= 1) {
                t  += __shfl_xor_sync(0xffffffffu, t, o);
                sq += __shfl_xor_sync(0xffffffffu, sq, o);
            }
            float mu   = t * (1.f/64.f);
            float rstd = rsqrtf(fmaf(sq, 1.f/64.f, -mu*mu) + 1e-5f);
            float m0 = fmaf((cur.x - mu) * rstd, g0, b0);
            float m1 = fmaf((cur.y - mu) * rstd, g1, b1);
            *(float2*)&sm->u.ab.mst[w][2*lane] = make_float2(m0, m1);
            __syncwarp();
            const float4 A0 = *(const float4*)&sm->u.ab.mst[w][seg*16 +  0];
            const float4 A1 = *(const float4*)&sm->u.ab.mst[w][seg*16 +  4];
            const float4 A2 = *(const float4*)&sm->u.ab.mst[w][seg*16 +  8];
            const float4 A3 = *(const float4*)&sm->u.ab.mst[w][seg*16 + 12];
            float acc = A0.x * qv0.x;
            acc = fmaf(A0.y, qv0.y, acc); acc = fmaf(A0.z, qv0.z, acc); acc = fmaf(A0.w, qv0.w, acc);
            acc = fmaf(A1.x, qv1.x, acc); acc = fmaf(A1.y, qv1.y, acc);
            acc = fmaf(A1.z, qv1.z, acc); acc = fmaf(A1.w, qv1.w, acc);
            acc = fmaf(A2.x, qv2.x, acc); acc = fmaf(A2.y, qv2.y, acc);
            acc = fmaf(A2.z, qv2.z, acc); acc = fmaf(A2.w, qv2.w, acc);
            acc = fmaf(A3.x, qv3.x, acc); acc = fmaf(A3.y, qv3.y, acc);
            acc = fmaf(A3.z, qv3.z, acc); acc = fmaf(A3.w, qv3.w, acc);
            acc += __shfl_xor_sync(0xffffffffu, acc, 1);
            acc += __shfl_xor_sync(0xffffffffu, acc, 2);
            float logit = acc + 1e9f * (cmk - 1.f);
            if (logit > rmax) {
                float alpha = __expf(rmax - logit);
                rZ *= alpha;
                #pragma unroll
                for (int i = 0; i < 16; i++) pwr[i] *= alpha;
                rmax = logit;
            }
            float e = __expf(logit - rmax);
            rZ += e;
            pwr[ 0] = fmaf(e, A0.x, pwr[ 0]); pwr[ 1] = fmaf(e, A0.y, pwr[ 1]);
            pwr[ 2] = fmaf(e, A0.z, pwr[ 2]); pwr[ 3] = fmaf(e, A0.w, pwr[ 3]);
            pwr[ 4] = fmaf(e, A1.x, pwr[ 4]); pwr[ 5] = fmaf(e, A1.y, pwr[ 5]);
            pwr[ 6] = fmaf(e, A1.z, pwr[ 6]); pwr[ 7] = fmaf(e, A1.w, pwr[ 7]);
            pwr[ 8] = fmaf(e, A2.x, pwr[ 8]); pwr[ 9] = fmaf(e, A2.y, pwr[ 9]);
            pwr[10] = fmaf(e, A2.z, pwr[10]); pwr[11] = fmaf(e, A2.w, pwr[11]);
            pwr[12] = fmaf(e, A3.x, pwr[12]); pwr[13] = fmaf(e, A3.y, pwr[13]);
            pwr[14] = fmaf(e, A3.z, pwr[14]); pwr[15] = fmaf(e, A3.w, pwr[15]);
            __syncwarp();
        }
        *(float4*)&sm->u.ab.pw[w][myh*64 + seg*16 +  0] = make_float4(pwr[ 0], pwr[ 1], pwr[ 2], pwr[ 3]);
        *(float4*)&sm->u.ab.pw[w][myh*64 + seg*16 +  4] = make_float4(pwr[ 4], pwr[ 5], pwr[ 6], pwr[ 7]);
        *(float4*)&sm->u.ab.pw[w][myh*64 + seg*16 +  8] = make_float4(pwr[ 8], pwr[ 9], pwr[10], pwr[11]);
        *(float4*)&sm->u.ab.pw[w][myh*64 + seg*16 + 12] = make_float4(pwr[12], pwr[13], pwr[14], pwr[15]);
        if (seg == 0) { sm->u.ab.wmax[w][myh] = rmax; sm->u.ab.wZ[w][myh] = rZ; }
    }
    __syncthreads();

    // combine warps
    if (tid < 8) {
        int h = tid;
        float gm = -3.4e38f;
        #pragma unroll
        for (int ww = 0; ww < 8; ww++) gm = fmaxf(gm, sm->u.ab.wmax[ww][h]);
        float Z = 0.f;
        #pragma unroll
        for (int ww = 0; ww < 8; ww++) Z += sm->u.ab.wZ[ww][h] * __expf(sm->u.ab.wmax[ww][h] - gm);
        sm->u.ab.gmax[h] = gm;
        sm->u.ab.Zt[h]   = Z;
    }
    __syncthreads();
    #pragma unroll
    for (int ii = 0; ii < 2; ii++) {
        int idx = tid + ii * 256;
        int h = idx >> 6;
        float gm = sm->u.ab.gmax[h];
        float a = 0.f;
        #pragma unroll
        for (int ww = 0; ww < 8; ww++)
            a = fmaf(sm->u.ab.pw[ww][idx], __expf(sm->u.ab.wmax[ww][h] - gm), a);
        sm->u.ab.pwt[idx] = a;
    }
    __syncthreads();
    // o[hc] = (pwt[h] @ Wv)[c] / Z[h]
    if (tid < 64) {
        int h = tid >> 3, c = tid & 7;
        float a = 0.f;
        #pragma unroll 8
        for (int d = 0; d < 64; d++) a = fmaf(sm->u.ab.pwt[h*64 + d], sm->Wv[d*8 + c], a);
        sm->oflat[tid] = a / sm->u.ab.Zt[h];
    }
    __syncthreads();

    // ================= Pass C: gate + output projection + residual =================
    {
        const float bg0 = sm->bgs[2*lane],  bg1 = sm->bgs[2*lane+1];
        const float oo0 = sm->oflat[2*lane], oo1 = sm->oflat[2*lane+1];
        const float bo0 = sm->bos[2*lane],  bo1 = sm->bos[2*lane+1];
        float* mp   = sm->u.c.mp[w];
        float* gost = sm->u.c.gost[w];

        for (int t = w; t < 256; t += 8) {
            const int sbase = t * 8;
            float2 xs[8];
            #pragma unroll
            for (int j = 0; j < 8; j++)
                xs[j] = *(const float2*)(Mraw + ((size_t)((sbase + j) * R_LEN + r)) * 64 + 2*lane);
            #pragma unroll
            for (int j = 0; j < 8; j++) {
                float tt = xs[j].x + xs[j].y, sq = fmaf(xs[j].x, xs[j].x, xs[j].y * xs[j].y);
                #pragma unroll
                for (int o = 16; o; o >>= 1) {
                    tt += __shfl_xor_sync(0xffffffffu, tt, o);
                    sq += __shfl_xor_sync(0xffffffffu, sq, o);
                }
                float mu   = tt * (1.f/64.f);
                float rstd = rsqrtf(fmaf(sq, 1.f/64.f, -mu*mu) + 1e-5f);
                float m0 = fmaf((xs[j].x - mu) * rstd, g0, b0);
                float m1 = fmaf((xs[j].y - mu) * rstd, g1, b1);
                int p = j >> 1, half = j & 1;
                mp[(p*64 + 2*lane    ) * 2 + half] = m0;
                mp[(p*64 + 2*lane + 1) * 2 + half] = m1;
            }
            __syncwarp();

            // GEMV1: G[s][hc] = m[s] @ Wg, hc = 2*lane, 2*lane+1, packed over s-pairs
            ull acc0[4] = {0,0,0,0}, acc1[4] = {0,0,0,0};
            #pragma unroll 8
            for (int d = 0; d < 64; d++) {
                float2 wp = *(float2*)&sm->Wg[d*64 + 2*lane];
                ull w0 = dup2(wp.x), w1 = dup2(wp.y);
                #pragma unroll
                for (int p = 0; p < 4; p++) {
                    ull a = *(ull*)&mp[(p*64 + d) * 2];
                    acc0[p] = ffma2(a, w0, acc0[p]);
                    acc1[p] = ffma2(a, w1, acc1[p]);
                }
            }
            // sigmoid gate * o, store transposed for GEMV2
            #pragma unroll
            for (int p = 0; p < 4; p++) {
                float2 a = unpack2(acc0[p]);
                a.x = sigmoidf(a.x + bg0) * oo0;
                a.y = sigmoidf(a.y + bg0) * oo0;
                *(ull*)&gost[(p*64 + 2*lane) * 2] = pack2(a.x, a.y);
                float2 bb = unpack2(acc1[p]);
                bb.x = sigmoidf(bb.x + bg1) * oo1;
                bb.y = sigmoidf(bb.y + bg1) * oo1;
                *(ull*)&gost[(p*64 + 2*lane + 1) * 2] = pack2(bb.x, bb.y);
            }
            __syncwarp();

            // GEMV2: out[s][d] = go[s] @ Wo, d = 2*lane, 2*lane+1
            ull accA[4] = {0,0,0,0}, accB[4] = {0,0,0,0};
            #pragma unroll 8
            for (int hc = 0; hc < 64; hc++) {
                float2 wp = *(float2*)&sm->Wo[hc*64 + 2*lane];
                ull w0 = dup2(wp.x), w1 = dup2(wp.y);
                #pragma unroll
                for (int p = 0; p < 4; p++) {
                    ull a = *(ull*)&gost[(p*64 + hc) * 2];
                    accA[p] = ffma2(a, w0, accA[p]);
                    accB[p] = ffma2(a, w1, accB[p]);
                }
            }
            // residual + store
            #pragma unroll
            for (int p = 0; p < 4; p++) {
                float2 A  = unpack2(accA[p]);
                float2 Bv = unpack2(accB[p]);
                int s0 = sbase + 2*p;
                *(float2*)(Out + ((size_t)(s0 * R_LEN + r)) * 64 + 2*lane) =
                    make_float2(A.x + bo0 + xs[2*p].x, Bv.x + bo1 + xs[2*p].y);
                *(float2*)(Out + ((size_t)((s0+1) * R_LEN + r)) * 64 + 2*lane) =
                    make_float2(A.y + bo0 + xs[2*p+1].x, Bv.y + bo1 + xs[2*p+1].y);
            }
            __syncwarp();
        }
    }
}

extern "C" void kernel_launch(void* const* d_in, const int* in_sizes, int n_in,
                              void* d_out, int out_size) {
    const float* Mraw  = (const float*)d_in[0];
    const float* Mmask = (const float*)d_in[1];
    const float* ln_g  = (const float*)d_in[2];
    const float* ln_b  = (const float*)d_in[3];
    const float* Wq    = (const float*)d_in[4];
    const float* Wk    = (const float*)d_in[5];
    const float* Wv    = (const float*)d_in[6];
    const float* Wg    = (const float*)d_in[7];
    const float* bg    = (const float*)d_in[8];
    const float* Wo    = (const float*)d_in[9];
    const float* bo    = (const float*)d_in[10];
    float* Out = (float*)d_out;

    cudaFuncSetAttribute(msa_col_global_attn,
                         cudaFuncAttributeMaxDynamicSharedMemorySize,
                         (int)sizeof(Smem));
    msa_col_global_attn<<<R_LEN, 256, sizeof(Smem)>>>(
        Mraw, Mmask, ln_g, ln_b, Wq, Wk, Wv, Wg, bg, Wo, bo, Out);
}